// round 8
// baseline (speedup 1.0000x reference)
#include <cuda_runtime.h>
#include <cuda_bf16.h>
#include <stdint.h>
#include <math.h>

// ---------------- problem constants ----------------
#define B_    8
#define S_    3072
#define H_    12
#define D_    128
#define E_    1536
#define NB_   256
#define CHUNK_ 12
#define CTX_  24
#define MTOK_ (B_*S_)         // 24576

#define OUT_MAIN  ((size_t)MTOK_ * E_)
#define ATTN_SZ   ((size_t)B_*H_*NB_*CHUNK_*CTX_)
#define WELEM_    (E_*E_)

#define QSCALE_BASE (0.088388347648318447f / 0.69314718055994531f)
#define KSCALE      (1.3132616875182228f  / 0.69314718055994531f)

// ---------------- scratch (device globals) ----------------
__device__ float g_q[OUT_MAIN];
__device__ float g_k[OUT_MAIN];
__device__ float g_v[OUT_MAIN];
__device__ float g_o[OUT_MAIN];
__device__ float g_relk[CTX_ * E_];
__device__ float g_qdscale[D_];

__device__ __nv_bfloat16 g_hs_hi[OUT_MAIN];
__device__ __nv_bfloat16 g_hs_lo[OUT_MAIN];
__device__ __nv_bfloat16 g_oc_hi[OUT_MAIN];
__device__ __nv_bfloat16 g_oc_lo[OUT_MAIN];
__device__ __nv_bfloat16 g_w_hi[5][WELEM_];
__device__ __nv_bfloat16 g_w_lo[5][WELEM_];
__device__ __nv_bfloat16 g_pe_hi[128 * E_];
__device__ __nv_bfloat16 g_pe_lo[128 * E_];

// ---------------- helpers ----------------
__device__ __forceinline__ void mma_bf16(float c[4], unsigned a0, unsigned a1,
                                         unsigned a2, unsigned a3,
                                         unsigned b0, unsigned b1){
    asm volatile(
        "mma.sync.aligned.m16n8k16.row.col.f32.bf16.bf16.f32 "
        "{%0,%1,%2,%3}, {%4,%5,%6,%7}, {%8,%9}, {%0,%1,%2,%3};"
        : "+f"(c[0]), "+f"(c[1]), "+f"(c[2]), "+f"(c[3])
        : "r"(a0), "r"(a1), "r"(a2), "r"(a3), "r"(b0), "r"(b1));
}
__device__ __forceinline__ void cpasync16(unsigned saddr, const void* gptr){
    asm volatile("cp.async.cg.shared.global [%0], [%1], 16;"
                 :: "r"(saddr), "l"(gptr) : "memory");
}
__device__ __forceinline__ void cpasync16z(unsigned saddr, const void* gptr, int sz){
    asm volatile("cp.async.cg.shared.global [%0], [%1], 16, %2;"
                 :: "r"(saddr), "l"(gptr), "r"(sz) : "memory");
}
__device__ __forceinline__ void ldsm4(unsigned r[4], unsigned addr){
    asm volatile("ldmatrix.sync.aligned.m8n8.x4.shared.b16 {%0,%1,%2,%3}, [%4];"
                 : "=r"(r[0]), "=r"(r[1]), "=r"(r[2]), "=r"(r[3]) : "r"(addr));
}

// ---------------- fp32 -> bf16 hi/lo split ----------------
__global__ void split_kernel(const float* __restrict__ src,
                             __nv_bfloat16* __restrict__ hi,
                             __nv_bfloat16* __restrict__ lo,
                             int nvalid4, int ntotal4)
{
    int i = blockIdx.x * 256 + threadIdx.x;
    if (i >= ntotal4) return;
    float4 x = (i < nvalid4) ? ((const float4*)src)[i] : make_float4(0.f,0.f,0.f,0.f);
    __nv_bfloat16 h0 = __float2bfloat16_rn(x.x);
    __nv_bfloat16 h1 = __float2bfloat16_rn(x.y);
    __nv_bfloat16 h2 = __float2bfloat16_rn(x.z);
    __nv_bfloat16 h3 = __float2bfloat16_rn(x.w);
    __nv_bfloat162* hp = (__nv_bfloat162*)(hi + (size_t)i * 4);
    hp[0] = __nv_bfloat162(h0, h1);
    hp[1] = __nv_bfloat162(h2, h3);
    __nv_bfloat162* lp = (__nv_bfloat162*)(lo + (size_t)i * 4);
    lp[0] = __nv_bfloat162(__float2bfloat16_rn(x.x - __bfloat162float(h0)),
                           __float2bfloat16_rn(x.y - __bfloat162float(h1)));
    lp[1] = __nv_bfloat162(__float2bfloat16_rn(x.z - __bfloat162float(h2)),
                           __float2bfloat16_rn(x.w - __bfloat162float(h3)));
}

__global__ void prep_scale_kernel(const float* __restrict__ pds, float* __restrict__ out)
{
    int d = threadIdx.x;
    if (d < D_) {
        float x = pds[d];
        float sp = (x > 20.f) ? x : log1pf(expf(x));
        out[d] = QSCALE_BASE * sp;
    }
}

// ============================================================================
// bf16x3 tensor-core NT GEMM, 128x256 CTA tile, 256 threads (8 warps, 2x4),
// warp tile 64x64, 3-stage cp.async pipeline, m16n8k16 bf16,
// 3 passes: Ah*Bh + Al*Bh + Ah*Bl. High register budget (occ 1).
// ============================================================================
#define BKH_   32                     // K halves per stage
#define LDAH_  40                     // 80B pitch (64B data + 16B pad)
#define AROWS_ 128
#define BROWS_ 256
#define ROWSST_ (2*AROWS_ + 2*BROWS_) // 768 rows per stage
#define STAGEB_ (ROWSST_ * LDAH_ * 2) // 61440 bytes
#define NSTAGE_ 3
#define SMEM_GEMM_ (NSTAGE_ * STAGEB_)// 184320

#define OFF_AH_ 0
#define OFF_AL_ (AROWS_ * LDAH_ * 2)
#define OFF_BH_ (2 * AROWS_ * LDAH_ * 2)
#define OFF_BL_ ((2 * AROWS_ + BROWS_) * LDAH_ * 2)

__global__ void __launch_bounds__(256)
gemm_bf16x3(const __nv_bfloat16* __restrict__ Ahi, const __nv_bfloat16* __restrict__ Alo,
            const __nv_bfloat16* __restrict__ Bhi, const __nv_bfloat16* __restrict__ Blo,
            float* __restrict__ C, int M, int N, int K,
            int mode, const float* __restrict__ colscale, float cscale)
{
    extern __shared__ char smem[];
    const unsigned sb = (unsigned)__cvta_generic_to_shared(smem);

    const int bm = blockIdx.y * 128;
    const int bn = blockIdx.x * 256;
    const int tid  = threadIdx.x;
    const int lane = tid & 31;
    const int warp = tid >> 5;
    const int wm = warp >> 2;       // 0..1 (M)
    const int wn = warp & 3;        // 0..3 (N)
    const int lr = lane >> 2;
    const int lc = lane & 3;

    float acc[4][8][4];
#pragma unroll
    for (int i = 0; i < 4; i++)
#pragma unroll
        for (int j = 0; j < 8; j++)
#pragma unroll
            for (int r = 0; r < 4; r++) acc[i][j][r] = 0.f;

    const int NK = K / BKH_;        // 48

    // ---- ldmatrix per-thread base offsets ----
    const int g  = lane >> 3;
    const int tr = lane & 7;
    unsigned aoff[4];
#pragma unroll
    for (int mt = 0; mt < 4; mt++) {
        const int row = wm * 64 + mt * 16 + (g & 1) * 8 + tr;
        const int col = (g >> 1) * 8;
        aoff[mt] = (unsigned)((row * LDAH_ + col) * 2);
    }
    unsigned boff[4];
#pragma unroll
    for (int n2 = 0; n2 < 4; n2++) {
        const int n = wn * 64 + n2 * 16 + (g >> 1) * 8 + tr;
        const int col = (g & 1) * 8;
        boff[n2] = (unsigned)((n * LDAH_ + col) * 2);
    }

    // ---- loader: 12 x 16B chunks per thread (3072 chunks per stage) ----
    auto issue_loads = [&](int it, int stage){
        const int kt = it * BKH_;
        const unsigned sbase = sb + stage * STAGEB_;
#pragma unroll
        for (int i = 0; i < 12; i++) {
            const int cid  = tid * 12 + i;       // 0..3071
            const int row  = cid >> 2;           // 0..767
            const int ch   = cid & 3;            // 16B chunk within 64B data
            const unsigned soff = (unsigned)(row * (LDAH_ * 2) + ch * 16);
            if (row < 2 * AROWS_) {
                const int ar = row & (AROWS_ - 1);
                const __nv_bfloat16* src = (row < AROWS_) ? Ahi : Alo;
                const int gr = bm + ar;
                const int sz = (gr < M) ? 16 : 0;
                const int grc = (gr < M) ? gr : 0;
                cpasync16z(sbase + soff, src + (size_t)grc * K + kt + ch * 8, sz);
            } else {
                const int br = (row - 2 * AROWS_) & (BROWS_ - 1);
                const __nv_bfloat16* src = (row < 2 * AROWS_ + BROWS_) ? Bhi : Blo;
                cpasync16(sbase + soff, src + (size_t)(bn + br) * K + kt + ch * 8);
            }
        }
        asm volatile("cp.async.commit_group;" ::: "memory");
    };

    issue_loads(0, 0);
    issue_loads(1, 1);

    int stage = 0;
    for (int it = 0; it < NK; it++) {
        if (it < NK - 1) asm volatile("cp.async.wait_group 1;" ::: "memory");
        else             asm volatile("cp.async.wait_group 0;" ::: "memory");
        __syncthreads();
        if (it + 2 < NK) {
            int ws = stage + 2; if (ws >= NSTAGE_) ws -= NSTAGE_;
            issue_loads(it + 2, ws);
        }

        const unsigned base = sb + stage * STAGEB_;
        const unsigned sAh = base + OFF_AH_;
        const unsigned sAl = base + OFF_AL_;
        const unsigned sBh = base + OFF_BH_;
        const unsigned sBl = base + OFF_BL_;

#pragma unroll
        for (int k0 = 0; k0 < BKH_; k0 += 16) {
            const unsigned kb = (unsigned)(k0 * 2);

            // pass 1: Ah * Bh
            unsigned ah[4][4], bh[4][4];
#pragma unroll
            for (int mt = 0; mt < 4; mt++) ldsm4(ah[mt], sAh + aoff[mt] + kb);
#pragma unroll
            for (int n2 = 0; n2 < 4; n2++) ldsm4(bh[n2], sBh + boff[n2] + kb);
#pragma unroll
            for (int mt = 0; mt < 4; mt++)
#pragma unroll
                for (int nt = 0; nt < 8; nt++)
                    mma_bf16(acc[mt][nt], ah[mt][0], ah[mt][1], ah[mt][2], ah[mt][3],
                             bh[nt >> 1][(nt & 1) * 2], bh[nt >> 1][(nt & 1) * 2 + 1]);

            // pass 2: Al * Bh
            unsigned xl[4][4];
#pragma unroll
            for (int mt = 0; mt < 4; mt++) ldsm4(xl[mt], sAl + aoff[mt] + kb);
#pragma unroll
            for (int mt = 0; mt < 4; mt++)
#pragma unroll
                for (int nt = 0; nt < 8; nt++)
                    mma_bf16(acc[mt][nt], xl[mt][0], xl[mt][1], xl[mt][2], xl[mt][3],
                             bh[nt >> 1][(nt & 1) * 2], bh[nt >> 1][(nt & 1) * 2 + 1]);

            // pass 3: Ah * Bl (reuse xl storage for bl)
#pragma unroll
            for (int n2 = 0; n2 < 4; n2++) ldsm4(xl[n2], sBl + boff[n2] + kb);
#pragma unroll
            for (int mt = 0; mt < 4; mt++)
#pragma unroll
                for (int nt = 0; nt < 8; nt++)
                    mma_bf16(acc[mt][nt], ah[mt][0], ah[mt][1], ah[mt][2], ah[mt][3],
                             xl[nt >> 1][(nt & 1) * 2], xl[nt >> 1][(nt & 1) * 2 + 1]);
        }
        stage++; if (stage >= NSTAGE_) stage = 0;
        __syncthreads();
    }

    // --- epilogue ---
#pragma unroll
    for (int mt = 0; mt < 4; mt++) {
#pragma unroll
        for (int nt = 0; nt < 8; nt++) {
            const int r0 = bm + wm * 64 + mt * 16 + lr;
            const int c0 = bn + wn * 64 + nt * 8 + 2 * lc;
            float v0 = acc[mt][nt][0], v1 = acc[mt][nt][1];
            float v2 = acc[mt][nt][2], v3 = acc[mt][nt][3];
            if (mode == 1) {
                const float s0 = colscale[c0 & (D_-1)], s1 = colscale[(c0+1) & (D_-1)];
                v0 *= s0; v1 *= s1; v2 *= s0; v3 *= s1;
            } else if (mode == 2) {
                v0 *= cscale; v1 *= cscale; v2 *= cscale; v3 *= cscale;
            }
            if (r0 < M)     *(float2*)(C + (size_t)r0      * N + c0) = make_float2(v0, v1);
            if (r0 + 8 < M) *(float2*)(C + (size_t)(r0+8)  * N + c0) = make_float2(v2, v3);
        }
    }
}

// ---------------- chunked local attention -----------------------------------
__global__ void __launch_bounds__(384)
attn_kernel(const float* __restrict__ q, const float* __restrict__ k,
            const float* __restrict__ v, const float* __restrict__ relk,
            float* __restrict__ o, float* __restrict__ attn_out)
{
    __shared__ float sq[CHUNK_][129];
    __shared__ float sk[CTX_][129];
    __shared__ float sv[CTX_][129];
    __shared__ float sr[CTX_][129];
    __shared__ float sac[CHUNK_][CTX_];
    __shared__ float sbd[CHUNK_][CTX_];
    __shared__ float sw[CHUNK_][25];

    const int n = blockIdx.x, h = blockIdx.y, b = blockIdx.z;
    const int t = threadIdx.x;

    for (int i = t; i < CHUNK_ * D_; i += 384) {
        const int c = i >> 7, d = i & 127;
        const int s = n * CHUNK_ + c;
        sq[c][d] = q[((size_t)(b * S_ + s)) * E_ + h * D_ + d];
    }
    for (int i = t; i < CTX_ * D_; i += 384) {
        const int j = i >> 7, d = i & 127;
        const int s = n * CHUNK_ - 12 + j;
        float kv = 0.f, vv = 0.f;
        if (s >= 0 && s < S_) {
            const size_t base = ((size_t)(b * S_ + s)) * E_ + h * D_ + d;
            kv = k[base]; vv = v[base];
        }
        sk[j][d] = kv;
        sv[j][d] = vv;
        sr[j][d] = relk[(size_t)j * E_ + h * D_ + d];
    }
    __syncthreads();

    for (int i = t; i < CHUNK_ * CTX_; i += 384) {
        const int c = i / CTX_, j = i % CTX_;
        float a = 0.f, bb = 0.f;
#pragma unroll 8
        for (int d = 0; d < D_; d++) {
            const float qq = sq[c][d];
            a  = fmaf(qq, sk[j][d], a);
            bb = fmaf(qq, sr[j][d], bb);
        }
        sac[c][j] = a;
        sbd[c][j] = bb;
    }
    __syncthreads();

    for (int i = t; i < CHUNK_ * CTX_; i += 384) {
        const int c = i / CTX_, j = i % CTX_;
        const int idx = c * CTX_ + j;
        const int r = idx / (CTX_ + 1);
        const int p = idx % (CTX_ + 1);
        const float bd = (p < CTX_) ? sbd[r][p] : 0.f;
        float l = sac[c][j] + bd;
        l = 50.f * tanhf(l * 0.02f);
        sw[c][j] = l;
    }
    __syncthreads();

    if (t < CHUNK_) {
        const int c = t;
        float m = -1e30f;
        for (int j = 0; j < CTX_; j++) m = fmaxf(m, sw[c][j]);
        float sum = 0.f;
        for (int j = 0; j < CTX_; j++) { const float e = expf(sw[c][j] - m); sum += e; sw[c][j] = e; }
        const float inv = 1.f / sum;
        for (int j = 0; j < CTX_; j++) sw[c][j] *= inv;
    }
    __syncthreads();

    if (attn_out) {
        for (int i = t; i < CHUNK_ * CTX_; i += 384) {
            const int c = i / CTX_, j = i % CTX_;
            attn_out[((((size_t)b * H_ + h) * NB_ + n) * CHUNK_ + c) * CTX_ + j] = sw[c][j];
        }
    }

    for (int i = t; i < CHUNK_ * D_; i += 384) {
        const int c = i >> 7, d = i & 127;
        float acc = 0.f;
#pragma unroll
        for (int j = 0; j < CTX_; j++) acc = fmaf(sw[c][j], sv[j][d], acc);
        o[((size_t)(b * S_ + n * CHUNK_ + c)) * E_ + h * D_ + d] = acc;
    }
}

// ---------------- launch -----------------------------------------------------
extern "C" void kernel_launch(void* const* d_in, const int* in_sizes, int n_in,
                              void* d_out, int out_size)
{
    const float* hs   = (const float*)d_in[0];
    const float* pe   = (const float*)d_in[1];
    const float* w_q  = (const float*)d_in[2];
    const float* w_k  = (const float*)d_in[3];
    const float* w_v  = (const float*)d_in[4];
    const float* w_p  = (const float*)d_in[5];
    const float* w_r  = (const float*)d_in[6];
    const float* pds  = (const float*)d_in[7];
    float* out = (float*)d_out;

    float *q, *k, *v, *o, *rk, *qs;
    cudaGetSymbolAddress((void**)&q,  g_q);
    cudaGetSymbolAddress((void**)&k,  g_k);
    cudaGetSymbolAddress((void**)&v,  g_v);
    cudaGetSymbolAddress((void**)&o,  g_o);
    cudaGetSymbolAddress((void**)&rk, g_relk);
    cudaGetSymbolAddress((void**)&qs, g_qdscale);

    __nv_bfloat16 *hsh, *hsl, *och, *ocl, *wh, *wl, *peh, *pel;
    cudaGetSymbolAddress((void**)&hsh, g_hs_hi);
    cudaGetSymbolAddress((void**)&hsl, g_hs_lo);
    cudaGetSymbolAddress((void**)&och, g_oc_hi);
    cudaGetSymbolAddress((void**)&ocl, g_oc_lo);
    cudaGetSymbolAddress((void**)&wh,  g_w_hi);
    cudaGetSymbolAddress((void**)&wl,  g_w_lo);
    cudaGetSymbolAddress((void**)&peh, g_pe_hi);
    cudaGetSymbolAddress((void**)&pel, g_pe_lo);

    cudaFuncSetAttribute(gemm_bf16x3, cudaFuncAttributeMaxDynamicSharedMemorySize, SMEM_GEMM_);

    prep_scale_kernel<<<1, 128>>>(pds, qs);

    const int n4hs = (int)(OUT_MAIN / 4);
    split_kernel<<<(n4hs + 255) / 256, 256>>>(hs, hsh, hsl, n4hs, n4hs);
    const int n4w = WELEM_ / 4;
    split_kernel<<<(n4w + 255) / 256, 256>>>(w_q, wh + 0*(size_t)WELEM_, wl + 0*(size_t)WELEM_, n4w, n4w);
    split_kernel<<<(n4w + 255) / 256, 256>>>(w_k, wh + 1*(size_t)WELEM_, wl + 1*(size_t)WELEM_, n4w, n4w);
    split_kernel<<<(n4w + 255) / 256, 256>>>(w_v, wh + 2*(size_t)WELEM_, wl + 2*(size_t)WELEM_, n4w, n4w);
    split_kernel<<<(n4w + 255) / 256, 256>>>(w_p, wh + 3*(size_t)WELEM_, wl + 3*(size_t)WELEM_, n4w, n4w);
    split_kernel<<<(n4w + 255) / 256, 256>>>(w_r, wh + 4*(size_t)WELEM_, wl + 4*(size_t)WELEM_, n4w, n4w);
    const int n4pe_v = CTX_ * E_ / 4, n4pe_t = 128 * E_ / 4;
    split_kernel<<<(n4pe_t + 255) / 256, 256>>>(pe, peh, pel, n4pe_v, n4pe_t);

    const dim3 gBig(E_ / 256, MTOK_ / 128);   // (6, 192)
    gemm_bf16x3<<<gBig, 256, SMEM_GEMM_>>>(hsh, hsl, wh + 0*(size_t)WELEM_, wl + 0*(size_t)WELEM_,
                                           q, MTOK_, E_, E_, 1, qs, 1.f);
    gemm_bf16x3<<<gBig, 256, SMEM_GEMM_>>>(hsh, hsl, wh + 1*(size_t)WELEM_, wl + 1*(size_t)WELEM_,
                                           k, MTOK_, E_, E_, 2, nullptr, KSCALE);
    gemm_bf16x3<<<gBig, 256, SMEM_GEMM_>>>(hsh, hsl, wh + 2*(size_t)WELEM_, wl + 2*(size_t)WELEM_,
                                           v, MTOK_, E_, E_, 0, nullptr, 1.f);
    gemm_bf16x3<<<dim3(E_ / 256, 1), 256, SMEM_GEMM_>>>(peh, pel, wh + 4*(size_t)WELEM_, wl + 4*(size_t)WELEM_,
                                           rk, CTX_, E_, E_, 0, nullptr, 1.f);

    float* attn = ((size_t)out_size >= OUT_MAIN + ATTN_SZ) ? (out + OUT_MAIN) : nullptr;
    attn_kernel<<<dim3(NB_, H_, B_), 384>>>(q, k, v, rk, o, attn);

    split_kernel<<<(n4hs + 255) / 256, 256>>>(o, och, ocl, n4hs, n4hs);
    gemm_bf16x3<<<gBig, 256, SMEM_GEMM_>>>(och, ocl, wh + 3*(size_t)WELEM_, wl + 3*(size_t)WELEM_,
                                           out, MTOK_, E_, E_, 0, nullptr, 1.f);
}

// round 9
// speedup vs baseline: 1.7645x; 1.7645x over previous
#include <cuda_runtime.h>
#include <cuda_bf16.h>
#include <stdint.h>
#include <math.h>

// ---------------- problem constants ----------------
#define B_    8
#define S_    3072
#define H_    12
#define D_    128
#define E_    1536
#define NB_   256
#define CHUNK_ 12
#define CTX_  24
#define MTOK_ (B_*S_)         // 24576

#define OUT_MAIN  ((size_t)MTOK_ * E_)
#define ATTN_SZ   ((size_t)B_*H_*NB_*CHUNK_*CTX_)
#define WELEM_    (E_*E_)

#define QSCALE_BASE (0.088388347648318447f / 0.69314718055994531f)
#define KSCALE      (1.3132616875182228f  / 0.69314718055994531f)

// ---------------- scratch (device globals) ----------------
__device__ float g_q[OUT_MAIN];
__device__ float g_k[OUT_MAIN];
__device__ float g_v[OUT_MAIN];
__device__ float g_o[OUT_MAIN];
__device__ float g_relk[CTX_ * E_];
__device__ float g_qdscale[D_];

// tiled+swizzled bf16 hi/lo operand storage
__device__ __nv_bfloat16 g_hs_hi[OUT_MAIN];
__device__ __nv_bfloat16 g_hs_lo[OUT_MAIN];
__device__ __nv_bfloat16 g_oc_hi[OUT_MAIN];
__device__ __nv_bfloat16 g_oc_lo[OUT_MAIN];
__device__ __nv_bfloat16 g_w_hi[5][WELEM_];
__device__ __nv_bfloat16 g_w_lo[5][WELEM_];
__device__ __nv_bfloat16 g_pe_hi[128 * E_];
__device__ __nv_bfloat16 g_pe_lo[128 * E_];

// ---------------- helpers ----------------
__device__ __forceinline__ void mma_bf16(float c[4], unsigned a0, unsigned a1,
                                         unsigned a2, unsigned a3,
                                         unsigned b0, unsigned b1){
    asm volatile(
        "mma.sync.aligned.m16n8k16.row.col.f32.bf16.bf16.f32 "
        "{%0,%1,%2,%3}, {%4,%5,%6,%7}, {%8,%9}, {%0,%1,%2,%3};"
        : "+f"(c[0]), "+f"(c[1]), "+f"(c[2]), "+f"(c[3])
        : "r"(a0), "r"(a1), "r"(a2), "r"(a3), "r"(b0), "r"(b1));
}
__device__ __forceinline__ void ldsm4(unsigned r[4], unsigned addr){
    asm volatile("ldmatrix.sync.aligned.m8n8.x4.shared.b16 {%0,%1,%2,%3}, [%4];"
                 : "=r"(r[0]), "=r"(r[1]), "=r"(r[2]), "=r"(r[3]) : "r"(addr));
}
__device__ __forceinline__ void bulk_cp(unsigned dst, const void* src, unsigned bytes,
                                        unsigned mbar){
    asm volatile(
        "cp.async.bulk.shared::cluster.global.mbarrier::complete_tx::bytes "
        "[%0], [%1], %2, [%3];"
        :: "r"(dst), "l"(src), "r"(bytes), "r"(mbar) : "memory");
}
#define MBAR_INIT(addr, cnt) \
    asm volatile("mbarrier.init.shared.b64 [%0], %1;" :: "r"(addr), "r"(cnt) : "memory")
#define MBAR_EXPECT_TX(addr, bytes) \
    asm volatile("mbarrier.arrive.expect_tx.shared.b64 _, [%0], %1;" \
                 :: "r"(addr), "r"(bytes) : "memory")
#define MBAR_WAIT(mbar, parity) do {                                        \
    asm volatile(                                                           \
        "{\n\t.reg .pred P1;\n\t"                                           \
        "WL_%=:\n\t"                                                        \
        "mbarrier.try_wait.parity.acquire.cta.shared::cta.b64 P1, [%0], %1, 0x989680;\n\t" \
        "@P1 bra.uni WD_%=;\n\t"                                            \
        "bra.uni WL_%=;\n\t"                                                \
        "WD_%=:\n\t}"                                                       \
        :: "r"(mbar), "r"(parity) : "memory");                              \
} while (0)

// ---------------- fp32 -> bf16 hi/lo split into tiled+swizzled layout -------
__device__ __forceinline__ unsigned pack2hi(float a, float b){
    __nv_bfloat162 t(__float2bfloat16_rn(a), __float2bfloat16_rn(b));
    return *(unsigned*)&t;
}
__device__ __forceinline__ unsigned pack2lo(float a, float b){
    float ha = __bfloat162float(__float2bfloat16_rn(a));
    float hb = __bfloat162float(__float2bfloat16_rn(b));
    __nv_bfloat162 t(__float2bfloat16_rn(a - ha), __float2bfloat16_rn(b - hb));
    return *(unsigned*)&t;
}

// A-type: 128-row tiles of 128B rows (64 halves), SW128 swizzled, 16KB/tile
__global__ void split_tiled_A(const float* __restrict__ src,
                              __nv_bfloat16* __restrict__ hi,
                              __nv_bfloat16* __restrict__ lo,
                              int Mvalid, int Mpad, int K)
{
    const int id = blockIdx.x * 256 + threadIdx.x;
    const int CK = K >> 3;                 // 8-float chunks per row
    if (id >= Mpad * CK) return;
    const int m = id / CK, c = id % CK;
    float4 x0 = make_float4(0.f,0.f,0.f,0.f), x1 = x0;
    if (m < Mvalid) {
        const float4* s = (const float4*)(src + (size_t)m * K + c * 8);
        x0 = s[0]; x1 = s[1];
    }
    const size_t tile = (size_t)(m >> 7) * (K >> 6) + (c >> 3);
    const unsigned inner = (unsigned)((m & 127) * 128 + (((c & 7) * 16) ^ ((m & 7) * 16)));
    uint4 h = make_uint4(pack2hi(x0.x,x0.y), pack2hi(x0.z,x0.w),
                         pack2hi(x1.x,x1.y), pack2hi(x1.z,x1.w));
    uint4 l = make_uint4(pack2lo(x0.x,x0.y), pack2lo(x0.z,x0.w),
                         pack2lo(x1.x,x1.y), pack2lo(x1.z,x1.w));
    *(uint4*)((char*)hi + tile * 16384 + inner) = h;
    *(uint4*)((char*)lo + tile * 16384 + inner) = l;
}

// B-type: 256-row tiles of 128B rows, SW128 swizzled, 32KB/tile
__global__ void split_tiled_B(const float* __restrict__ src,
                              __nv_bfloat16* __restrict__ hi,
                              __nv_bfloat16* __restrict__ lo,
                              int N, int K)
{
    const int id = blockIdx.x * 256 + threadIdx.x;
    const int CK = K >> 3;
    if (id >= N * CK) return;
    const int n = id / CK, c = id % CK;
    const float4* s = (const float4*)(src + (size_t)n * K + c * 8);
    float4 x0 = s[0], x1 = s[1];
    const size_t tile = (size_t)(n >> 8) * (K >> 6) + (c >> 3);
    const unsigned inner = (unsigned)((n & 255) * 128 + (((c & 7) * 16) ^ ((n & 7) * 16)));
    uint4 h = make_uint4(pack2hi(x0.x,x0.y), pack2hi(x0.z,x0.w),
                         pack2hi(x1.x,x1.y), pack2hi(x1.z,x1.w));
    uint4 l = make_uint4(pack2lo(x0.x,x0.y), pack2lo(x0.z,x0.w),
                         pack2lo(x1.x,x1.y), pack2lo(x1.z,x1.w));
    *(uint4*)((char*)hi + tile * 32768 + inner) = h;
    *(uint4*)((char*)lo + tile * 32768 + inner) = l;
}

__global__ void prep_scale_kernel(const float* __restrict__ pds, float* __restrict__ out)
{
    int d = threadIdx.x;
    if (d < D_) {
        float x = pds[d];
        float sp = (x > 20.f) ? x : log1pf(expf(x));
        out[d] = QSCALE_BASE * sp;
    }
}

// ============================================================================
// bf16x3 tensor-core NT GEMM with cp.async.bulk tile loads.
// 128x256 CTA tile, 256 threads (8 warps 2x4), warp tile 64x64,
// BK=64 halves, 2-stage mbarrier pipeline, m16n8k16 bf16, 3 passes.
// ============================================================================
#define TILEA_B  16384                 // A tile bytes (128 x 128B)
#define TILEB_B  32768                 // B tile bytes (256 x 128B)
#define STB_     (2*TILEA_B + 2*TILEB_B)   // 98304 per stage
#define SMEM_GEMM_ (2*STB_ + 128)          // 196736

#define SOFF_AH_ 0
#define SOFF_AL_ TILEA_B
#define SOFF_BH_ (2*TILEA_B)
#define SOFF_BL_ (2*TILEA_B + TILEB_B)

__global__ void __launch_bounds__(256)
gemm_bulk(const __nv_bfloat16* __restrict__ Aht, const __nv_bfloat16* __restrict__ Alt,
          const __nv_bfloat16* __restrict__ Bht, const __nv_bfloat16* __restrict__ Blt,
          float* __restrict__ C, int M, int N, int K,
          int mode, const float* __restrict__ colscale, float cscale)
{
    extern __shared__ char smem[];
    const unsigned sb = (unsigned)__cvta_generic_to_shared(smem);
    const unsigned mb0 = sb + 2 * STB_;      // two mbarriers at +196608, +196616

    const int tid  = threadIdx.x;
    const int lane = tid & 31;
    const int warp = tid >> 5;
    const int wm = warp >> 2;       // 0..1 (M)
    const int wn = warp & 3;        // 0..3 (N)
    const int lr = lane >> 2;
    const int lc = lane & 3;

    const int KT = K >> 6;          // 24 K-tiles
    const int aTile = blockIdx.y * KT;
    const int bTile = blockIdx.x * KT;

    if (tid == 0) { MBAR_INIT(mb0, 1); MBAR_INIT(mb0 + 8, 1); }
    __syncthreads();

    float acc[4][8][4];
#pragma unroll
    for (int i = 0; i < 4; i++)
#pragma unroll
        for (int j = 0; j < 8; j++)
#pragma unroll
            for (int r = 0; r < 4; r++) acc[i][j][r] = 0.f;

    // ---- ldmatrix per-thread offsets (SW128 swizzled 128B rows) ----
    const int g  = lane >> 3;
    const int tr = lane & 7;
    unsigned aoff[4], aswz[4];
#pragma unroll
    for (int mt = 0; mt < 4; mt++) {
        const int row = wm * 64 + mt * 16 + (g & 1) * 8 + tr;
        aoff[mt] = (unsigned)(row * 128);
        aswz[mt] = (unsigned)((row & 7) * 16);
    }
    const unsigned alane = (unsigned)((g >> 1) * 16);
    unsigned boff[4], bswz[4];
#pragma unroll
    for (int n2 = 0; n2 < 4; n2++) {
        const int n = wn * 64 + n2 * 16 + (g >> 1) * 8 + tr;
        boff[n2] = (unsigned)(n * 128);
        bswz[n2] = (unsigned)((n & 7) * 16);
    }
    const unsigned blane = (unsigned)((g & 1) * 16);

    auto issue = [&](int it, int s){
        if (tid == 0) {
            const unsigned mb = mb0 + s * 8;
            MBAR_EXPECT_TX(mb, (unsigned)STB_);
            const unsigned dst = sb + s * STB_;
            bulk_cp(dst + SOFF_AH_, (const char*)Aht + (size_t)(aTile + it) * TILEA_B, TILEA_B, mb);
            bulk_cp(dst + SOFF_AL_, (const char*)Alt + (size_t)(aTile + it) * TILEA_B, TILEA_B, mb);
            bulk_cp(dst + SOFF_BH_, (const char*)Bht + (size_t)(bTile + it) * TILEB_B, TILEB_B, mb);
            bulk_cp(dst + SOFF_BL_, (const char*)Blt + (size_t)(bTile + it) * TILEB_B, TILEB_B, mb);
        }
    };

    issue(0, 0);
    issue(1, 1);

    for (int it = 0; it < KT; it++) {
        const int s = it & 1;
        MBAR_WAIT(mb0 + s * 8, (unsigned)((it >> 1) & 1));

        const unsigned base = sb + s * STB_;
        const unsigned sAh = base + SOFF_AH_;
        const unsigned sAl = base + SOFF_AL_;
        const unsigned sBh = base + SOFF_BH_;
        const unsigned sBl = base + SOFF_BL_;

#pragma unroll
        for (int k0 = 0; k0 < 4; k0++) {
            const unsigned kb = (unsigned)(k0 * 32);

            // pass 1: Ah * Bh
            unsigned ah[4][4], bh[4][4];
#pragma unroll
            for (int mt = 0; mt < 4; mt++)
                ldsm4(ah[mt], sAh + aoff[mt] + ((kb + alane) ^ aswz[mt]));
#pragma unroll
            for (int n2 = 0; n2 < 4; n2++)
                ldsm4(bh[n2], sBh + boff[n2] + ((kb + blane) ^ bswz[n2]));
#pragma unroll
            for (int mt = 0; mt < 4; mt++)
#pragma unroll
                for (int nt = 0; nt < 8; nt++)
                    mma_bf16(acc[mt][nt], ah[mt][0], ah[mt][1], ah[mt][2], ah[mt][3],
                             bh[nt >> 1][(nt & 1) * 2], bh[nt >> 1][(nt & 1) * 2 + 1]);

            // pass 2: Al * Bh
            unsigned xl[4][4];
#pragma unroll
            for (int mt = 0; mt < 4; mt++)
                ldsm4(xl[mt], sAl + aoff[mt] + ((kb + alane) ^ aswz[mt]));
#pragma unroll
            for (int mt = 0; mt < 4; mt++)
#pragma unroll
                for (int nt = 0; nt < 8; nt++)
                    mma_bf16(acc[mt][nt], xl[mt][0], xl[mt][1], xl[mt][2], xl[mt][3],
                             bh[nt >> 1][(nt & 1) * 2], bh[nt >> 1][(nt & 1) * 2 + 1]);

            // pass 3: Ah * Bl (reuse xl for Bl)
#pragma unroll
            for (int n2 = 0; n2 < 4; n2++)
                ldsm4(xl[n2], sBl + boff[n2] + ((kb + blane) ^ bswz[n2]));
#pragma unroll
            for (int mt = 0; mt < 4; mt++)
#pragma unroll
                for (int nt = 0; nt < 8; nt++)
                    mma_bf16(acc[mt][nt], ah[mt][0], ah[mt][1], ah[mt][2], ah[mt][3],
                             xl[nt >> 1][(nt & 1) * 2], xl[nt >> 1][(nt & 1) * 2 + 1]);
        }
        __syncthreads();
        if (it + 2 < KT) issue(it + 2, s);
    }

    // --- epilogue ---
    const int bm = blockIdx.y * 128;
    const int bn = blockIdx.x * 256;
#pragma unroll
    for (int mt = 0; mt < 4; mt++) {
#pragma unroll
        for (int nt = 0; nt < 8; nt++) {
            const int r0 = bm + wm * 64 + mt * 16 + lr;
            const int c0 = bn + wn * 64 + nt * 8 + 2 * lc;
            float v0 = acc[mt][nt][0], v1 = acc[mt][nt][1];
            float v2 = acc[mt][nt][2], v3 = acc[mt][nt][3];
            if (mode == 1) {
                const float s0 = colscale[c0 & (D_-1)], s1 = colscale[(c0+1) & (D_-1)];
                v0 *= s0; v1 *= s1; v2 *= s0; v3 *= s1;
            } else if (mode == 2) {
                v0 *= cscale; v1 *= cscale; v2 *= cscale; v3 *= cscale;
            }
            if (r0 < M)     *(float2*)(C + (size_t)r0      * N + c0) = make_float2(v0, v1);
            if (r0 + 8 < M) *(float2*)(C + (size_t)(r0+8)  * N + c0) = make_float2(v2, v3);
        }
    }
}

// ---------------- chunked local attention -----------------------------------
__global__ void __launch_bounds__(384)
attn_kernel(const float* __restrict__ q, const float* __restrict__ k,
            const float* __restrict__ v, const float* __restrict__ relk,
            float* __restrict__ o, float* __restrict__ attn_out)
{
    __shared__ float sq[CHUNK_][129];
    __shared__ float sk[CTX_][129];
    __shared__ float sv[CTX_][129];
    __shared__ float sr[CTX_][129];
    __shared__ float sac[CHUNK_][CTX_];
    __shared__ float sbd[CHUNK_][CTX_];
    __shared__ float sw[CHUNK_][25];

    const int n = blockIdx.x, h = blockIdx.y, b = blockIdx.z;
    const int t = threadIdx.x;

    for (int i = t; i < CHUNK_ * D_; i += 384) {
        const int c = i >> 7, d = i & 127;
        const int s = n * CHUNK_ + c;
        sq[c][d] = q[((size_t)(b * S_ + s)) * E_ + h * D_ + d];
    }
    for (int i = t; i < CTX_ * D_; i += 384) {
        const int j = i >> 7, d = i & 127;
        const int s = n * CHUNK_ - 12 + j;
        float kv = 0.f, vv = 0.f;
        if (s >= 0 && s < S_) {
            const size_t base = ((size_t)(b * S_ + s)) * E_ + h * D_ + d;
            kv = k[base]; vv = v[base];
        }
        sk[j][d] = kv;
        sv[j][d] = vv;
        sr[j][d] = relk[(size_t)j * E_ + h * D_ + d];
    }
    __syncthreads();

    for (int i = t; i < CHUNK_ * CTX_; i += 384) {
        const int c = i / CTX_, j = i % CTX_;
        float a = 0.f, bb = 0.f;
#pragma unroll 8
        for (int d = 0; d < D_; d++) {
            const float qq = sq[c][d];
            a  = fmaf(qq, sk[j][d], a);
            bb = fmaf(qq, sr[j][d], bb);
        }
        sac[c][j] = a;
        sbd[c][j] = bb;
    }
    __syncthreads();

    for (int i = t; i < CHUNK_ * CTX_; i += 384) {
        const int c = i / CTX_, j = i % CTX_;
        const int idx = c * CTX_ + j;
        const int r = idx / (CTX_ + 1);
        const int p = idx % (CTX_ + 1);
        const float bd = (p < CTX_) ? sbd[r][p] : 0.f;
        float l = sac[c][j] + bd;
        l = 50.f * tanhf(l * 0.02f);
        sw[c][j] = l;
    }
    __syncthreads();

    if (t < CHUNK_) {
        const int c = t;
        float m = -1e30f;
        for (int j = 0; j < CTX_; j++) m = fmaxf(m, sw[c][j]);
        float sum = 0.f;
        for (int j = 0; j < CTX_; j++) { const float e = expf(sw[c][j] - m); sum += e; sw[c][j] = e; }
        const float inv = 1.f / sum;
        for (int j = 0; j < CTX_; j++) sw[c][j] *= inv;
    }
    __syncthreads();

    if (attn_out) {
        for (int i = t; i < CHUNK_ * CTX_; i += 384) {
            const int c = i / CTX_, j = i % CTX_;
            attn_out[((((size_t)b * H_ + h) * NB_ + n) * CHUNK_ + c) * CTX_ + j] = sw[c][j];
        }
    }

    for (int i = t; i < CHUNK_ * D_; i += 384) {
        const int c = i >> 7, d = i & 127;
        float acc = 0.f;
#pragma unroll
        for (int j = 0; j < CTX_; j++) acc = fmaf(sw[c][j], sv[j][d], acc);
        o[((size_t)(b * S_ + n * CHUNK_ + c)) * E_ + h * D_ + d] = acc;
    }
}

// ---------------- launch -----------------------------------------------------
extern "C" void kernel_launch(void* const* d_in, const int* in_sizes, int n_in,
                              void* d_out, int out_size)
{
    const float* hs   = (const float*)d_in[0];
    const float* pe   = (const float*)d_in[1];
    const float* w_q  = (const float*)d_in[2];
    const float* w_k  = (const float*)d_in[3];
    const float* w_v  = (const float*)d_in[4];
    const float* w_p  = (const float*)d_in[5];
    const float* w_r  = (const float*)d_in[6];
    const float* pds  = (const float*)d_in[7];
    float* out = (float*)d_out;

    float *q, *k, *v, *o, *rk, *qs;
    cudaGetSymbolAddress((void**)&q,  g_q);
    cudaGetSymbolAddress((void**)&k,  g_k);
    cudaGetSymbolAddress((void**)&v,  g_v);
    cudaGetSymbolAddress((void**)&o,  g_o);
    cudaGetSymbolAddress((void**)&rk, g_relk);
    cudaGetSymbolAddress((void**)&qs, g_qdscale);

    __nv_bfloat16 *hsh, *hsl, *och, *ocl, *wh, *wl, *peh, *pel;
    cudaGetSymbolAddress((void**)&hsh, g_hs_hi);
    cudaGetSymbolAddress((void**)&hsl, g_hs_lo);
    cudaGetSymbolAddress((void**)&och, g_oc_hi);
    cudaGetSymbolAddress((void**)&ocl, g_oc_lo);
    cudaGetSymbolAddress((void**)&wh,  g_w_hi);
    cudaGetSymbolAddress((void**)&wl,  g_w_lo);
    cudaGetSymbolAddress((void**)&peh, g_pe_hi);
    cudaGetSymbolAddress((void**)&pel, g_pe_lo);

    cudaFuncSetAttribute(gemm_bulk, cudaFuncAttributeMaxDynamicSharedMemorySize, SMEM_GEMM_);

    prep_scale_kernel<<<1, 128>>>(pds, qs);

    // tiled+swizzled splits
    const int tA = MTOK_ * (E_ / 8);
    split_tiled_A<<<(tA + 255) / 256, 256>>>(hs, hsh, hsl, MTOK_, MTOK_, E_);
    const int tB = E_ * (E_ / 8);
    split_tiled_B<<<(tB + 255) / 256, 256>>>(w_q, wh + 0*(size_t)WELEM_, wl + 0*(size_t)WELEM_, E_, E_);
    split_tiled_B<<<(tB + 255) / 256, 256>>>(w_k, wh + 1*(size_t)WELEM_, wl + 1*(size_t)WELEM_, E_, E_);
    split_tiled_B<<<(tB + 255) / 256, 256>>>(w_v, wh + 2*(size_t)WELEM_, wl + 2*(size_t)WELEM_, E_, E_);
    split_tiled_B<<<(tB + 255) / 256, 256>>>(w_p, wh + 3*(size_t)WELEM_, wl + 3*(size_t)WELEM_, E_, E_);
    split_tiled_B<<<(tB + 255) / 256, 256>>>(w_r, wh + 4*(size_t)WELEM_, wl + 4*(size_t)WELEM_, E_, E_);
    const int tPE = 128 * (E_ / 8);
    split_tiled_A<<<(tPE + 255) / 256, 256>>>(pe, peh, pel, CTX_, 128, E_);

    const dim3 gBig(E_ / 256, MTOK_ / 128);   // (6, 192)
    gemm_bulk<<<gBig, 256, SMEM_GEMM_>>>(hsh, hsl, wh + 0*(size_t)WELEM_, wl + 0*(size_t)WELEM_,
                                         q, MTOK_, E_, E_, 1, qs, 1.f);
    gemm_bulk<<<gBig, 256, SMEM_GEMM_>>>(hsh, hsl, wh + 1*(size_t)WELEM_, wl + 1*(size_t)WELEM_,
                                         k, MTOK_, E_, E_, 2, nullptr, KSCALE);
    gemm_bulk<<<gBig, 256, SMEM_GEMM_>>>(hsh, hsl, wh + 2*(size_t)WELEM_, wl + 2*(size_t)WELEM_,
                                         v, MTOK_, E_, E_, 0, nullptr, 1.f);
    gemm_bulk<<<dim3(E_ / 256, 1), 256, SMEM_GEMM_>>>(peh, pel, wh + 4*(size_t)WELEM_, wl + 4*(size_t)WELEM_,
                                         rk, CTX_, E_, E_, 0, nullptr, 1.f);

    float* attn = ((size_t)out_size >= OUT_MAIN + ATTN_SZ) ? (out + OUT_MAIN) : nullptr;
    attn_kernel<<<dim3(NB_, H_, B_), 384>>>(q, k, v, rk, o, attn);

    split_tiled_A<<<(tA + 255) / 256, 256>>>(o, och, ocl, MTOK_, MTOK_, E_);
    gemm_bulk<<<gBig, 256, SMEM_GEMM_>>>(och, ocl, wh + 3*(size_t)WELEM_, wl + 3*(size_t)WELEM_,
                                         out, MTOK_, E_, E_, 0, nullptr, 1.f);
}

// round 10
// speedup vs baseline: 2.0009x; 1.1340x over previous
#include <cuda_runtime.h>
#include <cuda_fp16.h>
#include <stdint.h>
#include <math.h>

// ---------------- problem constants ----------------
#define B_    8
#define S_    3072
#define H_    12
#define D_    128
#define E_    1536
#define NB_   256
#define CHUNK_ 12
#define CTX_  24
#define MTOK_ (B_*S_)         // 24576

#define OUT_MAIN  ((size_t)MTOK_ * E_)
#define ATTN_SZ   ((size_t)B_*H_*NB_*CHUNK_*CTX_)
#define WELEM_    (E_*E_)

#define QSCALE_BASE (0.088388347648318447f / 0.69314718055994531f)
#define KSCALE      (1.3132616875182228f  / 0.69314718055994531f)

// ---------------- scratch (device globals) ----------------
__device__ float g_q[OUT_MAIN];
__device__ float g_k[OUT_MAIN];
__device__ float g_v[OUT_MAIN];
__device__ float g_o[OUT_MAIN];
__device__ float g_relk[CTX_ * E_];
__device__ float g_qdscale[D_];

// tiled+swizzled fp16 hi/lo operand storage
__device__ __half g_hs_hi[OUT_MAIN];
__device__ __half g_hs_lo[OUT_MAIN];
__device__ __half g_oc_hi[OUT_MAIN];
__device__ __half g_oc_lo[OUT_MAIN];
__device__ __half g_w_hi[5][WELEM_];
__device__ __half g_w_lo[5][WELEM_];
__device__ __half g_pe_hi[128 * E_];
__device__ __half g_pe_lo[128 * E_];

// ---------------- helpers ----------------
__device__ __forceinline__ void mma_f16(float c[4], unsigned a0, unsigned a1,
                                        unsigned a2, unsigned a3,
                                        unsigned b0, unsigned b1){
    asm volatile(
        "mma.sync.aligned.m16n8k16.row.col.f32.f16.f16.f32 "
        "{%0,%1,%2,%3}, {%4,%5,%6,%7}, {%8,%9}, {%0,%1,%2,%3};"
        : "+f"(c[0]), "+f"(c[1]), "+f"(c[2]), "+f"(c[3])
        : "r"(a0), "r"(a1), "r"(a2), "r"(a3), "r"(b0), "r"(b1));
}
__device__ __forceinline__ void ldsm4(unsigned r[4], unsigned addr){
    asm volatile("ldmatrix.sync.aligned.m8n8.x4.shared.b16 {%0,%1,%2,%3}, [%4];"
                 : "=r"(r[0]), "=r"(r[1]), "=r"(r[2]), "=r"(r[3]) : "r"(addr));
}
__device__ __forceinline__ void bulk_cp(unsigned dst, const void* src, unsigned bytes,
                                        unsigned mbar){
    asm volatile(
        "cp.async.bulk.shared::cluster.global.mbarrier::complete_tx::bytes "
        "[%0], [%1], %2, [%3];"
        :: "r"(dst), "l"(src), "r"(bytes), "r"(mbar) : "memory");
}
#define MBAR_INIT(addr, cnt) \
    asm volatile("mbarrier.init.shared.b64 [%0], %1;" :: "r"(addr), "r"(cnt) : "memory")
#define MBAR_EXPECT_TX(addr, bytes) \
    asm volatile("mbarrier.arrive.expect_tx.shared.b64 _, [%0], %1;" \
                 :: "r"(addr), "r"(bytes) : "memory")
#define MBAR_WAIT(mbar, parity) do {                                        \
    asm volatile(                                                           \
        "{\n\t.reg .pred P1;\n\t"                                           \
        "WL_%=:\n\t"                                                        \
        "mbarrier.try_wait.parity.acquire.cta.shared::cta.b64 P1, [%0], %1, 0x989680;\n\t" \
        "@P1 bra.uni WD_%=;\n\t"                                            \
        "bra.uni WL_%=;\n\t"                                                \
        "WD_%=:\n\t}"                                                       \
        :: "r"(mbar), "r"(parity) : "memory");                              \
} while (0)

// ---------------- fp32 -> fp16 hi/lo split into tiled+swizzled layout -------
__device__ __forceinline__ unsigned pack2hi(float a, float b){
    __half2 t(__float2half_rn(a), __float2half_rn(b));
    return *(unsigned*)&t;
}
__device__ __forceinline__ unsigned pack2lo(float a, float b){
    float ha = __half2float(__float2half_rn(a));
    float hb = __half2float(__float2half_rn(b));
    __half2 t(__float2half_rn(a - ha), __float2half_rn(b - hb));
    return *(unsigned*)&t;
}

// A-type: 128-row tiles of 128B rows (64 halves), SW128 swizzled, 16KB/tile
__global__ void split_tiled_A(const float* __restrict__ src,
                              __half* __restrict__ hi,
                              __half* __restrict__ lo,
                              int Mvalid, int Mpad, int K)
{
    const int id = blockIdx.x * 256 + threadIdx.x;
    const int CK = K >> 3;                 // 8-float chunks per row
    if (id >= Mpad * CK) return;
    const int m = id / CK, c = id % CK;
    float4 x0 = make_float4(0.f,0.f,0.f,0.f), x1 = x0;
    if (m < Mvalid) {
        const float4* s = (const float4*)(src + (size_t)m * K + c * 8);
        x0 = s[0]; x1 = s[1];
    }
    const size_t tile = (size_t)(m >> 7) * (K >> 6) + (c >> 3);
    const unsigned inner = (unsigned)((m & 127) * 128 + (((c & 7) * 16) ^ ((m & 7) * 16)));
    uint4 h = make_uint4(pack2hi(x0.x,x0.y), pack2hi(x0.z,x0.w),
                         pack2hi(x1.x,x1.y), pack2hi(x1.z,x1.w));
    uint4 l = make_uint4(pack2lo(x0.x,x0.y), pack2lo(x0.z,x0.w),
                         pack2lo(x1.x,x1.y), pack2lo(x1.z,x1.w));
    *(uint4*)((char*)hi + tile * 16384 + inner) = h;
    *(uint4*)((char*)lo + tile * 16384 + inner) = l;
}

// B-type: 256-row tiles of 128B rows, SW128 swizzled, 32KB/tile
__global__ void split_tiled_B(const float* __restrict__ src,
                              __half* __restrict__ hi,
                              __half* __restrict__ lo,
                              int N, int K)
{
    const int id = blockIdx.x * 256 + threadIdx.x;
    const int CK = K >> 3;
    if (id >= N * CK) return;
    const int n = id / CK, c = id % CK;
    const float4* s = (const float4*)(src + (size_t)n * K + c * 8);
    float4 x0 = s[0], x1 = s[1];
    const size_t tile = (size_t)(n >> 8) * (K >> 6) + (c >> 3);
    const unsigned inner = (unsigned)((n & 255) * 128 + (((c & 7) * 16) ^ ((n & 7) * 16)));
    uint4 h = make_uint4(pack2hi(x0.x,x0.y), pack2hi(x0.z,x0.w),
                         pack2hi(x1.x,x1.y), pack2hi(x1.z,x1.w));
    uint4 l = make_uint4(pack2lo(x0.x,x0.y), pack2lo(x0.z,x0.w),
                         pack2lo(x1.x,x1.y), pack2lo(x1.z,x1.w));
    *(uint4*)((char*)hi + tile * 32768 + inner) = h;
    *(uint4*)((char*)lo + tile * 32768 + inner) = l;
}

__global__ void prep_scale_kernel(const float* __restrict__ pds, float* __restrict__ out)
{
    int d = threadIdx.x;
    if (d < D_) {
        float x = pds[d];
        float sp = (x > 20.f) ? x : log1pf(expf(x));
        out[d] = QSCALE_BASE * sp;
    }
}

// ============================================================================
// fp16 hi/lo tensor-core NT GEMM with cp.async.bulk tile loads.
// 128x256 CTA tile, 256 threads (8 warps 2x4), warp tile 64x64,
// BK=64 halves, 2-stage mbarrier pipeline, m16n8k16 f16.
// NPASS=3: Ah*Bh + Al*Bh + Ah*Bl (near-fp32).  NPASS=2: Ah*Bh + Al*Bh (=A*Bh).
// ============================================================================
#define TILEA_B  16384                 // A tile bytes (128 x 128B)
#define TILEB_B  32768                 // B tile bytes (256 x 128B)
#define STB_     (2*TILEA_B + 2*TILEB_B)   // 98304 per stage
#define SMEM_GEMM_ (2*STB_ + 128)          // 196736

#define SOFF_AH_ 0
#define SOFF_AL_ TILEA_B
#define SOFF_BH_ (2*TILEA_B)
#define SOFF_BL_ (2*TILEA_B + TILEB_B)

template<int NPASS>
__global__ void __launch_bounds__(256)
gemm_bulk(const __half* __restrict__ Aht, const __half* __restrict__ Alt,
          const __half* __restrict__ Bht, const __half* __restrict__ Blt,
          float* __restrict__ C, int M, int N, int K,
          int mode, const float* __restrict__ colscale, float cscale)
{
    extern __shared__ char smem[];
    const unsigned sb = (unsigned)__cvta_generic_to_shared(smem);
    const unsigned mb0 = sb + 2 * STB_;

    const int tid  = threadIdx.x;
    const int lane = tid & 31;
    const int warp = tid >> 5;
    const int wm = warp >> 2;       // 0..1 (M)
    const int wn = warp & 3;        // 0..3 (N)
    const int lr = lane >> 2;
    const int lc = lane & 3;

    const int KT = K >> 6;          // 24 K-tiles
    const int aTile = blockIdx.y * KT;
    const int bTile = blockIdx.x * KT;

    if (tid == 0) { MBAR_INIT(mb0, 1); MBAR_INIT(mb0 + 8, 1); }
    __syncthreads();

    float acc[4][8][4];
#pragma unroll
    for (int i = 0; i < 4; i++)
#pragma unroll
        for (int j = 0; j < 8; j++)
#pragma unroll
            for (int r = 0; r < 4; r++) acc[i][j][r] = 0.f;

    // ---- ldmatrix per-thread offsets (SW128 swizzled 128B rows) ----
    const int g  = lane >> 3;
    const int tr = lane & 7;
    unsigned aoff[4], aswz[4];
#pragma unroll
    for (int mt = 0; mt < 4; mt++) {
        const int row = wm * 64 + mt * 16 + (g & 1) * 8 + tr;
        aoff[mt] = (unsigned)(row * 128);
        aswz[mt] = (unsigned)((row & 7) * 16);
    }
    const unsigned alane = (unsigned)((g >> 1) * 16);
    unsigned boff[4], bswz[4];
#pragma unroll
    for (int n2 = 0; n2 < 4; n2++) {
        const int n = wn * 64 + n2 * 16 + (g >> 1) * 8 + tr;
        boff[n2] = (unsigned)(n * 128);
        bswz[n2] = (unsigned)((n & 7) * 16);
    }
    const unsigned blane = (unsigned)((g & 1) * 16);

    const unsigned stage_tx = (NPASS == 3) ? (unsigned)STB_ : (unsigned)(STB_ - TILEB_B);

    auto issue = [&](int it, int s){
        if (tid == 0) {
            const unsigned mb = mb0 + s * 8;
            MBAR_EXPECT_TX(mb, stage_tx);
            const unsigned dst = sb + s * STB_;
            bulk_cp(dst + SOFF_AH_, (const char*)Aht + (size_t)(aTile + it) * TILEA_B, TILEA_B, mb);
            bulk_cp(dst + SOFF_AL_, (const char*)Alt + (size_t)(aTile + it) * TILEA_B, TILEA_B, mb);
            bulk_cp(dst + SOFF_BH_, (const char*)Bht + (size_t)(bTile + it) * TILEB_B, TILEB_B, mb);
            if (NPASS == 3)
                bulk_cp(dst + SOFF_BL_, (const char*)Blt + (size_t)(bTile + it) * TILEB_B, TILEB_B, mb);
        }
    };

    issue(0, 0);
    issue(1, 1);

    for (int it = 0; it < KT; it++) {
        const int s = it & 1;
        MBAR_WAIT(mb0 + s * 8, (unsigned)((it >> 1) & 1));

        const unsigned base = sb + s * STB_;
        const unsigned sAh = base + SOFF_AH_;
        const unsigned sAl = base + SOFF_AL_;
        const unsigned sBh = base + SOFF_BH_;
        const unsigned sBl = base + SOFF_BL_;

#pragma unroll
        for (int k0 = 0; k0 < 4; k0++) {
            const unsigned kb = (unsigned)(k0 * 32);

            // pass 1: Ah * Bh
            unsigned ah[4][4], bh[4][4];
#pragma unroll
            for (int mt = 0; mt < 4; mt++)
                ldsm4(ah[mt], sAh + aoff[mt] + ((kb + alane) ^ aswz[mt]));
#pragma unroll
            for (int n2 = 0; n2 < 4; n2++)
                ldsm4(bh[n2], sBh + boff[n2] + ((kb + blane) ^ bswz[n2]));
#pragma unroll
            for (int mt = 0; mt < 4; mt++)
#pragma unroll
                for (int nt = 0; nt < 8; nt++)
                    mma_f16(acc[mt][nt], ah[mt][0], ah[mt][1], ah[mt][2], ah[mt][3],
                            bh[nt >> 1][(nt & 1) * 2], bh[nt >> 1][(nt & 1) * 2 + 1]);

            // pass 2: Al * Bh
            unsigned xl[4][4];
#pragma unroll
            for (int mt = 0; mt < 4; mt++)
                ldsm4(xl[mt], sAl + aoff[mt] + ((kb + alane) ^ aswz[mt]));
#pragma unroll
            for (int mt = 0; mt < 4; mt++)
#pragma unroll
                for (int nt = 0; nt < 8; nt++)
                    mma_f16(acc[mt][nt], xl[mt][0], xl[mt][1], xl[mt][2], xl[mt][3],
                            bh[nt >> 1][(nt & 1) * 2], bh[nt >> 1][(nt & 1) * 2 + 1]);

            // pass 3: Ah * Bl (reuse xl for Bl)
            if (NPASS == 3) {
#pragma unroll
                for (int n2 = 0; n2 < 4; n2++)
                    ldsm4(xl[n2], sBl + boff[n2] + ((kb + blane) ^ bswz[n2]));
#pragma unroll
                for (int mt = 0; mt < 4; mt++)
#pragma unroll
                    for (int nt = 0; nt < 8; nt++)
                        mma_f16(acc[mt][nt], ah[mt][0], ah[mt][1], ah[mt][2], ah[mt][3],
                                xl[nt >> 1][(nt & 1) * 2], xl[nt >> 1][(nt & 1) * 2 + 1]);
            }
        }
        __syncthreads();
        if (it + 2 < KT) issue(it + 2, s);
    }

    // --- epilogue ---
    const int bm = blockIdx.y * 128;
    const int bn = blockIdx.x * 256;
#pragma unroll
    for (int mt = 0; mt < 4; mt++) {
#pragma unroll
        for (int nt = 0; nt < 8; nt++) {
            const int r0 = bm + wm * 64 + mt * 16 + lr;
            const int c0 = bn + wn * 64 + nt * 8 + 2 * lc;
            float v0 = acc[mt][nt][0], v1 = acc[mt][nt][1];
            float v2 = acc[mt][nt][2], v3 = acc[mt][nt][3];
            if (mode == 1) {
                const float s0 = colscale[c0 & (D_-1)], s1 = colscale[(c0+1) & (D_-1)];
                v0 *= s0; v1 *= s1; v2 *= s0; v3 *= s1;
            } else if (mode == 2) {
                v0 *= cscale; v1 *= cscale; v2 *= cscale; v3 *= cscale;
            }
            if (r0 < M)     *(float2*)(C + (size_t)r0      * N + c0) = make_float2(v0, v1);
            if (r0 + 8 < M) *(float2*)(C + (size_t)(r0+8)  * N + c0) = make_float2(v2, v3);
        }
    }
}

// ---------------- chunked local attention -----------------------------------
__global__ void __launch_bounds__(384)
attn_kernel(const float* __restrict__ q, const float* __restrict__ k,
            const float* __restrict__ v, const float* __restrict__ relk,
            float* __restrict__ o, float* __restrict__ attn_out)
{
    __shared__ float sq[CHUNK_][129];
    __shared__ float sk[CTX_][129];
    __shared__ float sv[CTX_][129];
    __shared__ float sr[CTX_][129];
    __shared__ float sac[CHUNK_][CTX_];
    __shared__ float sbd[CHUNK_][CTX_];
    __shared__ float sw[CHUNK_][25];

    const int n = blockIdx.x, h = blockIdx.y, b = blockIdx.z;
    const int t = threadIdx.x;

    for (int i = t; i < CHUNK_ * D_; i += 384) {
        const int c = i >> 7, d = i & 127;
        const int s = n * CHUNK_ + c;
        sq[c][d] = q[((size_t)(b * S_ + s)) * E_ + h * D_ + d];
    }
    for (int i = t; i < CTX_ * D_; i += 384) {
        const int j = i >> 7, d = i & 127;
        const int s = n * CHUNK_ - 12 + j;
        float kv = 0.f, vv = 0.f;
        if (s >= 0 && s < S_) {
            const size_t base = ((size_t)(b * S_ + s)) * E_ + h * D_ + d;
            kv = k[base]; vv = v[base];
        }
        sk[j][d] = kv;
        sv[j][d] = vv;
        sr[j][d] = relk[(size_t)j * E_ + h * D_ + d];
    }
    __syncthreads();

    for (int i = t; i < CHUNK_ * CTX_; i += 384) {
        const int c = i / CTX_, j = i % CTX_;
        float a = 0.f, bb = 0.f;
#pragma unroll 8
        for (int d = 0; d < D_; d++) {
            const float qq = sq[c][d];
            a  = fmaf(qq, sk[j][d], a);
            bb = fmaf(qq, sr[j][d], bb);
        }
        sac[c][j] = a;
        sbd[c][j] = bb;
    }
    __syncthreads();

    for (int i = t; i < CHUNK_ * CTX_; i += 384) {
        const int c = i / CTX_, j = i % CTX_;
        const int idx = c * CTX_ + j;
        const int r = idx / (CTX_ + 1);
        const int p = idx % (CTX_ + 1);
        const float bd = (p < CTX_) ? sbd[r][p] : 0.f;
        float l = sac[c][j] + bd;
        l = 50.f * tanhf(l * 0.02f);
        sw[c][j] = l;
    }
    __syncthreads();

    if (t < CHUNK_) {
        const int c = t;
        float m = -1e30f;
        for (int j = 0; j < CTX_; j++) m = fmaxf(m, sw[c][j]);
        float sum = 0.f;
        for (int j = 0; j < CTX_; j++) { const float e = expf(sw[c][j] - m); sum += e; sw[c][j] = e; }
        const float inv = 1.f / sum;
        for (int j = 0; j < CTX_; j++) sw[c][j] *= inv;
    }
    __syncthreads();

    if (attn_out) {
        for (int i = t; i < CHUNK_ * CTX_; i += 384) {
            const int c = i / CTX_, j = i % CTX_;
            attn_out[((((size_t)b * H_ + h) * NB_ + n) * CHUNK_ + c) * CTX_ + j] = sw[c][j];
        }
    }

    for (int i = t; i < CHUNK_ * D_; i += 384) {
        const int c = i >> 7, d = i & 127;
        float acc = 0.f;
#pragma unroll
        for (int j = 0; j < CTX_; j++) acc = fmaf(sw[c][j], sv[j][d], acc);
        o[((size_t)(b * S_ + n * CHUNK_ + c)) * E_ + h * D_ + d] = acc;
    }
}

// ---------------- launch -----------------------------------------------------
extern "C" void kernel_launch(void* const* d_in, const int* in_sizes, int n_in,
                              void* d_out, int out_size)
{
    const float* hs   = (const float*)d_in[0];
    const float* pe   = (const float*)d_in[1];
    const float* w_q  = (const float*)d_in[2];
    const float* w_k  = (const float*)d_in[3];
    const float* w_v  = (const float*)d_in[4];
    const float* w_p  = (const float*)d_in[5];
    const float* w_r  = (const float*)d_in[6];
    const float* pds  = (const float*)d_in[7];
    float* out = (float*)d_out;

    float *q, *k, *v, *o, *rk, *qs;
    cudaGetSymbolAddress((void**)&q,  g_q);
    cudaGetSymbolAddress((void**)&k,  g_k);
    cudaGetSymbolAddress((void**)&v,  g_v);
    cudaGetSymbolAddress((void**)&o,  g_o);
    cudaGetSymbolAddress((void**)&rk, g_relk);
    cudaGetSymbolAddress((void**)&qs, g_qdscale);

    __half *hsh, *hsl, *och, *ocl, *wh, *wl, *peh, *pel;
    cudaGetSymbolAddress((void**)&hsh, g_hs_hi);
    cudaGetSymbolAddress((void**)&hsl, g_hs_lo);
    cudaGetSymbolAddress((void**)&och, g_oc_hi);
    cudaGetSymbolAddress((void**)&ocl, g_oc_lo);
    cudaGetSymbolAddress((void**)&wh,  g_w_hi);
    cudaGetSymbolAddress((void**)&wl,  g_w_lo);
    cudaGetSymbolAddress((void**)&peh, g_pe_hi);
    cudaGetSymbolAddress((void**)&pel, g_pe_lo);

    cudaFuncSetAttribute(gemm_bulk<3>, cudaFuncAttributeMaxDynamicSharedMemorySize, SMEM_GEMM_);
    cudaFuncSetAttribute(gemm_bulk<2>, cudaFuncAttributeMaxDynamicSharedMemorySize, SMEM_GEMM_);

    prep_scale_kernel<<<1, 128>>>(pds, qs);

    // tiled+swizzled fp16 splits
    const int tA = MTOK_ * (E_ / 8);
    split_tiled_A<<<(tA + 255) / 256, 256>>>(hs, hsh, hsl, MTOK_, MTOK_, E_);
    const int tB = E_ * (E_ / 8);
    split_tiled_B<<<(tB + 255) / 256, 256>>>(w_q, wh + 0*(size_t)WELEM_, wl + 0*(size_t)WELEM_, E_, E_);
    split_tiled_B<<<(tB + 255) / 256, 256>>>(w_k, wh + 1*(size_t)WELEM_, wl + 1*(size_t)WELEM_, E_, E_);
    split_tiled_B<<<(tB + 255) / 256, 256>>>(w_v, wh + 2*(size_t)WELEM_, wl + 2*(size_t)WELEM_, E_, E_);
    split_tiled_B<<<(tB + 255) / 256, 256>>>(w_p, wh + 3*(size_t)WELEM_, wl + 3*(size_t)WELEM_, E_, E_);
    split_tiled_B<<<(tB + 255) / 256, 256>>>(w_r, wh + 4*(size_t)WELEM_, wl + 4*(size_t)WELEM_, E_, E_);
    const int tPE = 128 * (E_ / 8);
    split_tiled_A<<<(tPE + 255) / 256, 256>>>(pe, peh, pel, CTX_, 128, E_);

    const dim3 gBig(E_ / 256, MTOK_ / 128);   // (6, 192)
    gemm_bulk<3><<<gBig, 256, SMEM_GEMM_>>>(hsh, hsl, wh + 0*(size_t)WELEM_, wl + 0*(size_t)WELEM_,
                                            q, MTOK_, E_, E_, 1, qs, 1.f);
    gemm_bulk<3><<<gBig, 256, SMEM_GEMM_>>>(hsh, hsl, wh + 1*(size_t)WELEM_, wl + 1*(size_t)WELEM_,
                                            k, MTOK_, E_, E_, 2, nullptr, KSCALE);
    gemm_bulk<2><<<gBig, 256, SMEM_GEMM_>>>(hsh, hsl, wh + 2*(size_t)WELEM_, wl + 2*(size_t)WELEM_,
                                            v, MTOK_, E_, E_, 0, nullptr, 1.f);
    gemm_bulk<3><<<dim3(E_ / 256, 1), 256, SMEM_GEMM_>>>(peh, pel, wh + 4*(size_t)WELEM_, wl + 4*(size_t)WELEM_,
                                            rk, CTX_, E_, E_, 0, nullptr, 1.f);

    float* attn = ((size_t)out_size >= OUT_MAIN + ATTN_SZ) ? (out + OUT_MAIN) : nullptr;
    attn_kernel<<<dim3(NB_, H_, B_), 384>>>(q, k, v, rk, o, attn);

    split_tiled_A<<<(tA + 255) / 256, 256>>>(o, och, ocl, MTOK_, MTOK_, E_);
    gemm_bulk<2><<<gBig, 256, SMEM_GEMM_>>>(och, ocl, wh + 3*(size_t)WELEM_, wl + 3*(size_t)WELEM_,
                                            out, MTOK_, E_, E_, 0, nullptr, 1.f);
}